// round 4
// baseline (speedup 1.0000x reference)
#include <cuda_runtime.h>
#include <math.h>

#define B    256
#define H    128
#define NL   4
#define V    32000
#define T    32
#define K4   512
#define BT   16
#define UT   16

typedef unsigned long long ull;

// ---------------- device scratch ----------------
__device__ float g_h[2][NL][B][H];
__device__ float g_c[2][NL][B][H];
__device__ float g_emb[B][H];
__device__ float g_M[B];
__device__ float g_inv[B];
__device__ int   g_prev[B];

// ---------------- packed f32x2 helpers ----------------
__device__ __forceinline__ ull pkc(float a, float b) {
    ull r;
    asm("mov.b64 %0, {%1, %2};" : "=l"(r) : "f"(a), "f"(b));
    return r;
}
__device__ __forceinline__ ull pk2(float x) {
    ull r;
    asm("mov.b64 %0, {%1, %1};" : "=l"(r) : "f"(x));
    return r;
}
__device__ __forceinline__ void fma2(ull &acc, ull a, ull b) {
    asm("fma.rn.f32x2 %0, %1, %2, %3;" : "=l"(acc) : "l"(a), "l"(b), "l"(acc));
}
__device__ __forceinline__ float2 upk(ull v) {
    float2 r;
    asm("mov.b64 {%0, %1}, %2;" : "=f"(r.x), "=f"(r.y) : "l"(v));
    return r;
}
__device__ __forceinline__ float sigm(float x) { return 1.0f / (1.0f + expf(-x)); }

// ---------------- init ----------------
__global__ void init_kernel(const float* __restrict__ hidden,
                            const float* __restrict__ cell,
                            const int*   __restrict__ eos) {
    int i = blockIdx.x * 256 + threadIdx.x;
    if (i < NL * B * H) {
        (&g_h[0][0][0][0])[i] = hidden[i];
        (&g_c[0][0][0][0])[i] = cell[i];
    }
    if (i < B) g_prev[i] = eos[0];
}

// ---------------- one LSTM layer (embedding gather fused into layer 0) ----------------
// grid (16, 8), 256 threads, dyn smem 49408 B
__global__ void lstm_kernel(int l, int rpar,
                            const float* __restrict__ W_in,
                            const float* __restrict__ b_in,
                            const float* __restrict__ W_ih,
                            const float* __restrict__ W_hh,
                            const float* __restrict__ b_ih,
                            const float* __restrict__ b_hh) {
    extern __shared__ char smraw[];
    float* xs  = (float*)smraw;            // [16][128]
    float* hs  = xs + BT * H;              // [16][128]
    ull*   wif = (ull*)(hs + BT * H);      // [16][129]
    ull*   wgo = wif + UT * 129;           // [16][129]

    const int wpar = rpar ^ 1;
    const int b0 = blockIdx.x * BT, u0 = blockIdx.y * UT;
    const int tid = threadIdx.x;

    const float* hold = &g_h[rpar][l][0][0];
    if (l == 0) {
        for (int i = tid; i < BT * H; i += 256) {
            int bl = i >> 7, k = i & 127;
            int tok = g_prev[b0 + bl];
            xs[i] = W_in[tok * H + k] + b_in[k];
            hs[i] = hold[(b0 + bl) * H + k];
        }
    } else {
        const float* xin = &g_h[wpar][l - 1][0][0];
        for (int i = tid; i < BT * H; i += 256) {
            int bl = i >> 7, k = i & 127;
            xs[i] = xin[(b0 + bl) * H + k];
            hs[i] = hold[(b0 + bl) * H + k];
        }
    }

    const int ul = tid & 15, bl = tid >> 4;
    ull aif = 0ull, ago = 0ull;    // packed (i,f) / (g,o)

    for (int p = 0; p < 2; p++) {
        const float* Wb = (p ? W_hh : W_ih) + l * K4 * H;
        __syncthreads();
        for (int i = tid; i < UT * H; i += 256) {
            int uu = i >> 7, k = i & 127;
            int r = (u0 + uu) * H + k;
            wif[uu * 129 + k] = pkc(Wb[r],           Wb[r + 128 * H]);
            wgo[uu * 129 + k] = pkc(Wb[r + 256 * H], Wb[r + 384 * H]);
        }
        __syncthreads();
        const float* src  = (p ? hs : xs) + bl * H;
        const ull*   wifu = wif + ul * 129;
        const ull*   wgou = wgo + ul * 129;
#pragma unroll 4
        for (int k = 0; k < H; k++) {
            ull e2 = pk2(src[k]);
            fma2(aif, e2, wifu[k]);
            fma2(ago, e2, wgou[k]);
        }
    }

    const int b = b0 + bl, u = u0 + ul;
    float2 vif = upk(aif), vgo = upk(ago);
    const float* bi = b_ih + l * K4;
    const float* bh = b_hh + l * K4;
    float gi = vif.x + bi[u]       + bh[u];
    float gf = vif.y + bi[u + 128] + bh[u + 128];
    float gg = vgo.x + bi[u + 256] + bh[u + 256];
    float go = vgo.y + bi[u + 384] + bh[u + 384];
    float co = g_c[rpar][l][b][u];
    float cn = sigm(gf) * co + sigm(gi) * tanhf(gg);
    float hn = sigm(go) * tanhf(cn);
    g_c[wpar][l][b][u] = cn;
    g_h[wpar][l][b][u] = hn;
}

// ---------------- emb = h_last @ W_re.T + b_re ----------------
// grid 32, 128 threads, dyn smem 70144 B
__global__ void emb_kernel(int wpar,
                           const float* __restrict__ W_re,
                           const float* __restrict__ b_re) {
    extern __shared__ char smraw[];
    float* Wt  = (float*)smraw;        // [128k][129]: Wt[k*129+e]
    float* hsm = Wt + H * 129;         // [8][128]
    const int tid = threadIdx.x;
    const int b0 = blockIdx.x * 8;

    for (int i = tid; i < H * H; i += 128) {
        int e = i >> 7, k = i & 127;
        Wt[k * 129 + e] = W_re[e * H + k];
    }
    for (int i = tid; i < 8 * H; i += 128) {
        hsm[i] = g_h[wpar][NL - 1][b0 + (i >> 7)][i & 127];
    }
    __syncthreads();

    const int e = tid;
    const float br = b_re[e];
#pragma unroll
    for (int bl = 0; bl < 8; bl++) {
        float acc = 0.0f;
#pragma unroll 4
        for (int k = 0; k < H; k++)
            acc = fmaf(hsm[bl * H + k], Wt[k * 129 + e], acc);
        g_emb[b0 + bl][e] = acc + br;
    }
}

// ---------------- logits = emb @ W_lo.T + b_lo (fp32 via FFMA2) ----------------
// grid (250, 4): 128 v x 64 b per block; 256 threads; dyn smem 134144 B
// smem: Wp [128k][66] ull (v-pairs, pitch 66 for 16B row alignment)
//       ed [64b][130] ull (emb duplicated)
__global__ void logits_kernel(const float* __restrict__ W_lo,
                              const float* __restrict__ b_lo,
                              float* __restrict__ out) {
    extern __shared__ char smraw[];
    ull* Wp = (ull*)smraw;            // 128*66
    ull* ed = Wp + 128 * 66;          // 64*130

    const int tid = threadIdx.x;
    const int v0 = blockIdx.x * 128;
    const int b0 = blockIdx.y * 64;

    // stage W tile as v-pairs: 64 vpairs x 128 k
    for (int i = tid; i < 64 * 128; i += 256) {
        int vp = i >> 7, k = i & 127;
        const float* w = W_lo + (v0 + 2 * vp) * H + k;
        Wp[k * 66 + vp] = pkc(w[0], w[H]);
    }
    // stage duplicated emb: 64 b x 128 k
    for (int i = tid; i < 64 * 128; i += 256) {
        int bb = i >> 7, k = i & 127;
        ed[bb * 130 + k] = pk2(g_emb[b0 + bb][k]);
    }
    __syncthreads();

    const int vpg = tid & 31;   // lane: 2 v-pairs -> 4 v
    const int bg  = tid >> 5;   // warp: 8 batch rows

    ull acc[8][2];
#pragma unroll
    for (int j = 0; j < 8; j++) { acc[j][0] = 0ull; acc[j][1] = 0ull; }

    const ull* wp = Wp + 2 * vpg;
    const ull* ep = ed + bg * 8 * 130;
#pragma unroll 2
    for (int k = 0; k < H; k++) {
        ulonglong2 w01 = *(const ulonglong2*)(wp + k * 66);  // LDS.128, conflict-free
#pragma unroll
        for (int j = 0; j < 8; j++) {
            ull e = ep[j * 130 + k];                          // broadcast
            fma2(acc[j][0], e, w01.x);
            fma2(acc[j][1], e, w01.y);
        }
    }

    const int v = v0 + 4 * vpg;
    const float4 bl4 = *(const float4*)(b_lo + v);
#pragma unroll
    for (int j = 0; j < 8; j++) {
        float2 r0 = upk(acc[j][0]), r1 = upk(acc[j][1]);
        float4 o;
        o.x = r0.x + bl4.x;
        o.y = r0.y + bl4.y;
        o.z = r1.x + bl4.z;
        o.w = r1.y + bl4.w;
        *(float4*)(out + (size_t)(b0 + bg * 8 + j) * V + v) = o;  // coalesced STG.128
    }
}

// ---------------- per-row max / argmax(first) / sum-exp ----------------
__global__ void smax_kernel(const float* __restrict__ lg) {
    __shared__ float sm_m[256];
    __shared__ float sm_s[256];
    __shared__ int   sm_i[256];
    const int b = blockIdx.x, tid = threadIdx.x;
    const float* row = lg + (size_t)b * V;

    float m = -1e30f, s = 0.0f;
    int idx = 0x7fffffff;
    for (int v = tid; v < V; v += 256) {
        float l = row[v];
        if (l > m) { s = s * expf(m - l) + 1.0f; m = l; idx = v; }
        else       { s += expf(l - m); }
    }
    sm_m[tid] = m; sm_s[tid] = s; sm_i[tid] = idx;
    __syncthreads();
    for (int off = 128; off; off >>= 1) {
        if (tid < off) {
            float m1 = sm_m[tid], m2 = sm_m[tid + off];
            float s1 = sm_s[tid], s2 = sm_s[tid + off];
            int   i1 = sm_i[tid], i2 = sm_i[tid + off];
            float M = fmaxf(m1, m2);
            sm_s[tid] = s1 * expf(m1 - M) + s2 * expf(m2 - M);
            sm_m[tid] = M;
            sm_i[tid] = (m1 > m2) ? i1 : ((m2 > m1) ? i2 : min(i1, i2));
        }
        __syncthreads();
    }
    if (tid == 0) {
        g_M[b]    = sm_m[0];
        g_inv[b]  = 1.0f / sm_s[0];
        g_prev[b] = sm_i[0];
    }
}

// ---------------- in-place normalize ----------------
__global__ void norm_kernel(float* __restrict__ lg) {
    const int b = blockIdx.x, tid = threadIdx.x;
    float* row = lg + (size_t)b * V;
    const float M = g_M[b], inv = g_inv[b];
    for (int v = tid; v < V; v += 256)
        row[v] = expf(row[v] - M) * inv;
}

// ---------------- launch ----------------
extern "C" void kernel_launch(void* const* d_in, const int* in_sizes, int n_in,
                              void* d_out, int out_size) {
    const float* hidden = (const float*)d_in[0];
    const float* cell   = (const float*)d_in[1];
    const float* W_in   = (const float*)d_in[2];
    const float* b_in   = (const float*)d_in[3];
    const float* W_ih   = (const float*)d_in[4];
    const float* W_hh   = (const float*)d_in[5];
    const float* b_ih   = (const float*)d_in[6];
    const float* b_hh   = (const float*)d_in[7];
    const float* W_re   = (const float*)d_in[8];
    const float* b_re   = (const float*)d_in[9];
    const float* W_lo   = (const float*)d_in[10];
    const float* b_lo   = (const float*)d_in[11];
    const int*   eos    = (const int*)d_in[12];
    float* out = (float*)d_out;

    const int SM_LSTM = 49408, SM_EMB = 70144, SM_LOG = 134144;
    cudaFuncSetAttribute(lstm_kernel,   cudaFuncAttributeMaxDynamicSharedMemorySize, SM_LSTM);
    cudaFuncSetAttribute(emb_kernel,    cudaFuncAttributeMaxDynamicSharedMemorySize, SM_EMB);
    cudaFuncSetAttribute(logits_kernel, cudaFuncAttributeMaxDynamicSharedMemorySize, SM_LOG);

    init_kernel<<<(NL * B * H + 255) / 256, 256>>>(hidden, cell, eos);

    for (int t = 0; t < T; t++) {
        int rpar = t & 1;
        for (int l = 0; l < NL; l++)
            lstm_kernel<<<dim3(B / BT, H / UT), 256, SM_LSTM>>>(
                l, rpar, W_in, b_in, W_ih, W_hh, b_ih, b_hh);
        emb_kernel<<<32, 128, SM_EMB>>>(rpar ^ 1, W_re, b_re);
        float* lgt = out + (size_t)t * B * V;
        logits_kernel<<<dim3(V / 128, B / 64), 256, SM_LOG>>>(W_lo, b_lo, lgt);
        smax_kernel<<<B, 256>>>(lgt);
        norm_kernel<<<B, 256>>>(lgt);
    }
}

// round 5
// speedup vs baseline: 1.0346x; 1.0346x over previous
#include <cuda_runtime.h>
#include <math.h>

#define BATCH 256
#define H     128
#define NL    4
#define V     32000
#define TSTEP 32
#define NB    128
#define NT    1024
#define NVT   250      // v-tiles of 128

typedef unsigned long long ull;

// ---------------- device scratch (no allocation allowed) ----------------
__device__ __align__(16) float g_h[2][NL][BATCH][H];
__device__ __align__(16) float g_c[2][NL][BATCH][H];
__device__ __align__(16) float g_emb[BATCH][H];
__device__ __align__(16) float g_scr[BATCH][V];   // logits scratch, L2-resident
__device__ int g_prev[BATCH];
__device__ int c_init, c_h[NL], c_emb, c_log, c_red, c_norm, c_done;

// ---------------- packed f32x2 helpers ----------------
__device__ __forceinline__ ull pkc(float a, float b) {
    ull r; asm("mov.b64 %0, {%1, %2};" : "=l"(r) : "f"(a), "f"(b)); return r;
}
__device__ __forceinline__ ull pk2(float x) {
    ull r; asm("mov.b64 %0, {%1, %1};" : "=l"(r) : "f"(x)); return r;
}
__device__ __forceinline__ void fma2(ull &acc, ull a, ull b) {
    asm("fma.rn.f32x2 %0, %1, %2, %3;" : "=l"(acc) : "l"(a), "l"(b), "l"(acc));
}
__device__ __forceinline__ float2 upk(ull v) {
    float2 r; asm("mov.b64 {%0, %1}, %2;" : "=f"(r.x), "=f"(r.y) : "l"(v)); return r;
}
__device__ __forceinline__ float sigm(float x) { return 1.0f / (1.0f + expf(-x)); }

// ---------------- dataflow sync primitives ----------------
__device__ __forceinline__ void waitcnt(int* c, int target) {
    if (threadIdx.x == 0) {
        volatile int* vc = (volatile int*)c;
        while (*vc < target) __nanosleep(64);
        __threadfence();
    }
    __syncthreads();
}
__device__ __forceinline__ void bumpcnt(int* c) {
    __syncthreads();
    if (threadIdx.x == 0) { __threadfence(); atomicAdd(c, 1); }
}

// ============================================================================
// One persistent kernel: init + 32 x (4 LSTM layers, emb, logits, softmax)
// 128 blocks x 1024 threads, 1 block/SM, all co-resident (grid < SM count).
// ============================================================================
__global__ void __launch_bounds__(NT, 1)
decoder_kernel(const float* __restrict__ hidden, const float* __restrict__ cell,
               const float* __restrict__ W_in,  const float* __restrict__ b_in,
               const float* __restrict__ W_ih,  const float* __restrict__ W_hh,
               const float* __restrict__ b_ih,  const float* __restrict__ b_hh,
               const float* __restrict__ W_re,  const float* __restrict__ b_re,
               const float* __restrict__ W_lo,  const float* __restrict__ b_lo,
               const int*   __restrict__ eos,
               float* __restrict__ out)
{
    extern __shared__ ull sm[];
    ull* smA = sm;            // 8256 ull: persistent LSTM weights (32 chains x 258)
    ull* smB = sm + 8256;     // 8448 ull: Wp / xs / emb-Wt / reduce arrays
    ull* smC = smB + 8448;    // 8320 ull: ed / hs / hsm

    const int tid = threadIdx.x;
    const int bid = blockIdx.x;
    const int ut  = bid & 31, q = bid >> 5;
    const int u0  = ut * 4,  b0 = q * 64;

    // ---- persistent LSTM weight slice -> smA (once per launch) ----
    // chain ci = l*8 + ul*2 + ch; [0..127]=x-part (W_ih), [128..255]=h-part (W_hh)
    // ch0 packs gates (i, f) = rows (u, u+128); ch1 packs (g, o) = (u+256, u+384)
    for (int j = tid; j < 32 * 256; j += NT) {
        int ci = j >> 8, k = j & 255;
        int l = ci >> 3, ul = (ci >> 1) & 3, ch = ci & 1;
        int u = u0 + ul;
        const float* Ws = ((k < 128) ? W_ih : W_hh) + l * 512 * H;
        int kk = k & 127;
        int g0 = ch ? (u + 256) : u;
        smA[ci * 258 + k] = pkc(Ws[g0 * H + kk], Ws[(g0 + 128) * H + kk]);
    }

    // ---- init state (each block copies its 1024-element share) ----
    {
        int j = bid * 1024 + tid;                 // NL*BATCH*H = 131072 = 128*1024
        __stcg(&(&g_h[0][0][0][0])[j], hidden[j]);
        __stcg(&(&g_c[0][0][0][0])[j], cell[j]);
        if (bid == 0 && tid < BATCH) __stcg(&g_prev[tid], __ldg(&eos[0]));
    }
    bumpcnt(&c_init);
    waitcnt(&c_init, NB);

    for (int t = 0; t < TSTEP; t++) {
        const int rp = t & 1, wp = rp ^ 1;

        // ================= LSTM: 4 layers, all 128 blocks per layer =========
        for (int l = 0; l < NL; l++) {
            if (l == 0) waitcnt(&c_red, NB * t);               // g_prev + all t-1 done
            else        waitcnt(&c_h[l - 1], NB * (t + 1));    // this-step layer l-1

            ull* xs = smB;   // [64][129] duplicated f32x2
            ull* hs = smC;   // [64][129]
            if (l == 0) {
                for (int j = tid; j < 64 * H; j += NT) {
                    int bl = j >> 7, k = j & 127;
                    int tok = __ldcg(&g_prev[b0 + bl]);
                    xs[bl * 129 + k] = pk2(__ldg(&W_in[tok * H + k]) + __ldg(&b_in[k]));
                }
            } else {
                for (int j = tid; j < 64 * H; j += NT) {
                    int bl = j >> 7, k = j & 127;
                    xs[bl * 129 + k] = pk2(__ldcg(&g_h[wp][l - 1][b0 + bl][k]));
                }
            }
            for (int j = tid; j < 64 * H; j += NT) {
                int bl = j >> 7, k = j & 127;
                hs[bl * 129 + k] = pk2(__ldcg(&g_h[rp][l][b0 + bl][k]));
            }
            __syncthreads();

            if (tid < 512) {
                int bl = tid >> 3, ul = (tid >> 1) & 3, ch = tid & 1;
                const ull* w  = smA + ((l * 4 + ul) * 2 + ch) * 258;  // stride 258: no bank conflict
                const ull* xv = xs + bl * 129;
                const ull* hv = hs + bl * 129;
                ull acc = 0ull;
#pragma unroll 4
                for (int k = 0; k < H; k++) fma2(acc, xv[k], w[k]);
#pragma unroll 4
                for (int k = 0; k < H; k++) fma2(acc, hv[k], w[128 + k]);
                float2 vv = upk(acc);
                int u = u0 + ul, b = b0 + bl;
                int gA = ch ? (u + 256) : u;
                float a0 = vv.x + __ldg(&b_ih[l * 512 + gA])       + __ldg(&b_hh[l * 512 + gA]);
                float a1 = vv.y + __ldg(&b_ih[l * 512 + gA + 128]) + __ldg(&b_hh[l * 512 + gA + 128]);
                float p0 = __shfl_xor_sync(0xffffffffu, a0, 1);    // partner's (g,o) / (i,f)
                float p1 = __shfl_xor_sync(0xffffffffu, a1, 1);
                if (ch == 0) {   // this thread holds (i,f)=(a0,a1), partner gave (g,o)=(p0,p1)
                    float co = __ldcg(&g_c[rp][l][b][u]);
                    float cn = sigm(a1) * co + sigm(a0) * tanhf(p0);
                    float hn = sigm(p1) * tanhf(cn);
                    __stcg(&g_c[wp][l][b][u], cn);
                    __stcg(&g_h[wp][l][b][u], hn);
                }
            }
            bumpcnt(&c_h[l]);
        }

        // ================= emb = h_last @ W_re.T + b_re  (blocks 0..31) =====
        if (bid < 32) {
            waitcnt(&c_h[NL - 1], NB * (t + 1));
            float* Wt  = (float*)smB;     // [128k][129]
            float* hsm = (float*)smC;     // [8][128]
            int eb0 = bid * 8;
            for (int j = tid; j < H * H; j += NT) {
                int e = j >> 7, k = j & 127;
                Wt[k * 129 + e] = __ldg(&W_re[e * H + k]);
            }
            for (int j = tid; j < 8 * H; j += NT)
                hsm[j] = __ldcg(&g_h[wp][NL - 1][eb0 + (j >> 7)][j & 127]);
            __syncthreads();
            int bl = tid >> 7, e = tid & 127;
            float acc = 0.f;
#pragma unroll 4
            for (int k = 0; k < H; k++)
                acc = fmaf(hsm[bl * 128 + k], Wt[k * 129 + e], acc);
            __stcg(&g_emb[eb0 + bl][e], acc + __ldg(&b_re[e]));
            bumpcnt(&c_emb);
        }

        // ================= logits -> g_scr (all blocks) =====================
        waitcnt(&c_emb, 32 * (t + 1));
        waitcnt(&c_norm, NB * t);          // scratch free (prev-step norm done)
        {
            ull* Wp = smB;                 // [128k][66] v-pairs (pitch 66: 16B-aligned pairs)
            ull* ed = smC;                 // [64b][128] duplicated emb
            int vq = tid & 31, bg = tid >> 5;
            for (int tt = bid; tt < NVT; tt += NB) {
                int v0 = tt * 128;
                __syncthreads();
                for (int j = tid; j < 64 * H; j += NT) {
                    int vp = j >> 7, k = j & 127;
                    const float* wl = W_lo + (size_t)(v0 + 2 * vp) * H + k;
                    Wp[k * 66 + vp] = pkc(wl[0], wl[H]);
                }
                for (int qq = 0; qq < 4; qq++) {
                    __syncthreads();
                    for (int j = tid; j < 64 * H; j += NT) {
                        int bb = j >> 7, k = j & 127;
                        ed[bb * 128 + k] = pk2(__ldcg(&g_emb[qq * 64 + bb][k]));
                    }
                    __syncthreads();
                    ull a00 = 0, a01 = 0, a10 = 0, a11 = 0;
                    const ull* wrow = Wp + 2 * vq;
                    const ull* e0 = ed + (2 * bg) * 128;
                    const ull* e1 = e0 + 128;
#pragma unroll 2
                    for (int k = 0; k < H; k++) {
                        ulonglong2 w2 = *(const ulonglong2*)(wrow + k * 66); // LDS.128, conflict-free
                        ull ea = e0[k], eb = e1[k];                          // broadcast
                        fma2(a00, ea, w2.x); fma2(a01, ea, w2.y);
                        fma2(a10, eb, w2.x); fma2(a11, eb, w2.y);
                    }
                    int v  = v0 + 4 * vq;
                    int br = qq * 64 + 2 * bg;
                    float4 bl4 = *(const float4*)(b_lo + v);
                    float2 r0 = upk(a00), r1 = upk(a01);
                    float4 o;
                    o.x = r0.x + bl4.x; o.y = r0.y + bl4.y; o.z = r1.x + bl4.z; o.w = r1.y + bl4.w;
                    __stcg((float4*)&g_scr[br][v], o);
                    r0 = upk(a10); r1 = upk(a11);
                    o.x = r0.x + bl4.x; o.y = r0.y + bl4.y; o.z = r1.x + bl4.z; o.w = r1.y + bl4.w;
                    __stcg((float4*)&g_scr[br + 1][v], o);
                }
            }
        }
        bumpcnt(&c_log);

        // ====== fused softmax: reduce (max/argmax/sum) + normalize, 2 rows/block
        waitcnt(&c_log, NB * (t + 1));
        {
            float* mS = (float*)smB;
            float* sS = mS + 1024;
            int*   iS = (int*)(sS + 1024);
            int half = tid >> 9, lane = tid & 511;
            int r = 2 * bid + half;
            float m = -1e30f, s = 0.f; int idx = V;
            for (int v = lane; v < V; v += 512) {
                float lv = __ldcg(&g_scr[r][v]);
                if (lv > m) { s = s * __expf(m - lv) + 1.f; m = lv; idx = v; }
                else        { s += __expf(lv - m); }
            }
            mS[tid] = m; sS[tid] = s; iS[tid] = idx;
            __syncthreads();
            for (int off = 256; off > 0; off >>= 1) {
                if (lane < off) {
                    float m1 = mS[tid], m2 = mS[tid + off];
                    float s1 = sS[tid], s2 = sS[tid + off];
                    int   i1 = iS[tid], i2 = iS[tid + off];
                    float M = fmaxf(m1, m2);
                    sS[tid] = s1 * __expf(m1 - M) + s2 * __expf(m2 - M);
                    mS[tid] = M;
                    iS[tid] = (m1 > m2) ? i1 : ((m2 > m1) ? i2 : min(i1, i2));
                }
                __syncthreads();
            }
            float M   = mS[half << 9];
            float inv = 1.f / sS[half << 9];
            if (lane == 0) __stcg(&g_prev[r], iS[half << 9]);
            bumpcnt(&c_red);    // unblocks step t+1 LSTM; norm below overlaps it
            float* orow = out + ((size_t)t * BATCH + r) * V;
            for (int v = lane; v < V; v += 512) {
                float lv = __ldcg(&g_scr[r][v]);
                __stcs(&orow[v], __expf(lv - M) * inv);
            }
        }
        bumpcnt(&c_norm);
    }

    // ---- epilogue: reset counters so graph replays start clean ----
    __syncthreads();
    if (tid == 0) {
        __threadfence();
        atomicAdd(&c_done, 1);
        if (bid == 0) {
            volatile int* vd = (volatile int*)&c_done;
            while (*vd < NB) __nanosleep(64);
            c_init = 0; c_emb = 0; c_log = 0; c_red = 0; c_norm = 0;
            for (int l = 0; l < NL; l++) c_h[l] = 0;
            __threadfence();
            *(volatile int*)&c_done = 0;
        }
    }
}

// ---------------- launch ----------------
extern "C" void kernel_launch(void* const* d_in, const int* in_sizes, int n_in,
                              void* d_out, int out_size) {
    const float* hidden = (const float*)d_in[0];
    const float* cell   = (const float*)d_in[1];
    const float* W_in   = (const float*)d_in[2];
    const float* b_in   = (const float*)d_in[3];
    const float* W_ih   = (const float*)d_in[4];
    const float* W_hh   = (const float*)d_in[5];
    const float* b_ih   = (const float*)d_in[6];
    const float* b_hh   = (const float*)d_in[7];
    const float* W_re   = (const float*)d_in[8];
    const float* b_re   = (const float*)d_in[9];
    const float* W_lo   = (const float*)d_in[10];
    const float* b_lo   = (const float*)d_in[11];
    const int*   eos    = (const int*)d_in[12];
    float* out = (float*)d_out;

    const int SMEM = 25024 * 8;   // 200192 B dynamic
    cudaFuncSetAttribute(decoder_kernel, cudaFuncAttributeMaxDynamicSharedMemorySize, SMEM);

    decoder_kernel<<<NB, NT, SMEM>>>(hidden, cell, W_in, b_in, W_ih, W_hh,
                                     b_ih, b_hh, W_re, b_re, W_lo, b_lo, eos, out);
}

// round 6
// speedup vs baseline: 1.4958x; 1.4459x over previous
#include <cuda_runtime.h>
#include <math.h>

#define BATCH 256
#define H     128
#define NL    4
#define V     32000
#define TSTEP 32
#define NB    128
#define NT    1024
#define NVT   250      // v-tiles of 128

typedef unsigned long long ull;

// ---------------- device scratch ----------------
__device__ __align__(16) float g_h[2][NL][BATCH][H];
__device__ __align__(16) float g_c[2][NL][BATCH][H];
__device__ __align__(16) float g_embT[H * BATCH];     // [k][row] == pair layout as ull
__device__ __align__(16) float g_scr[BATCH][V];       // logits scratch, L2-resident
__device__ int g_prev[BATCH];
__device__ int c_init, c_h[NL], c_emb, c_log, c_red, c_norm, c_done;

// ---------------- packed f32x2 helpers ----------------
__device__ __forceinline__ ull pk2(float x) {
    ull r; asm("mov.b64 %0, {%1, %1};" : "=l"(r) : "f"(x)); return r;
}
__device__ __forceinline__ ull pkc(float a, float b) {
    ull r; asm("mov.b64 %0, {%1, %2};" : "=l"(r) : "f"(a), "f"(b)); return r;
}
__device__ __forceinline__ void fma2(ull &acc, ull a, ull b) {
    asm("fma.rn.f32x2 %0, %1, %2, %3;" : "=l"(acc) : "l"(a), "l"(b), "l"(acc));
}
__device__ __forceinline__ float2 upk(ull v) {
    float2 r; asm("mov.b64 {%0, %1}, %2;" : "=f"(r.x), "=f"(r.y) : "l"(v)); return r;
}
__device__ __forceinline__ float sigm(float x) { return 1.0f / (1.0f + expf(-x)); }

// ---------------- dataflow sync ----------------
__device__ __forceinline__ void waitcnt(int* c, int target) {
    if (threadIdx.x == 0) {
        volatile int* vc = (volatile int*)c;
        while (*vc < target) __nanosleep(64);
        __threadfence();
    }
    __syncthreads();
}
__device__ __forceinline__ void bumpcnt(int* c) {
    __syncthreads();
    if (threadIdx.x == 0) { __threadfence(); atomicAdd(c, 1); }
}

// ============================================================================
// Persistent kernel: 128 blocks x 1024 threads, 1 block/SM, all co-resident.
// ============================================================================
__global__ void __launch_bounds__(NT, 1)
decoder_kernel(const float* __restrict__ hidden, const float* __restrict__ cell,
               const float* __restrict__ W_in,  const float* __restrict__ b_in,
               const float* __restrict__ W_ih,  const float* __restrict__ W_hh,
               const float* __restrict__ b_ih,  const float* __restrict__ b_hh,
               const float* __restrict__ W_re,  const float* __restrict__ b_re,
               const float* __restrict__ W_lo,  const float* __restrict__ b_lo,
               const int*   __restrict__ eos,
               float* __restrict__ out)
{
    extern __shared__ char smraw[];
    const int tid = threadIdx.x;
    const int bid = blockIdx.x;

    // ---- init state ----
    {
        int j = bid * NT + tid;                    // NL*BATCH*H = 131072 = 128*1024
        __stcg(&(&g_h[0][0][0][0])[j], hidden[j]);
        __stcg(&(&g_c[0][0][0][0])[j], cell[j]);
        if (bid == 0 && tid < BATCH) __stcg(&g_prev[tid], __ldg(&eos[0]));
    }
    bumpcnt(&c_init);
    waitcnt(&c_init, NB);

    // block roles
    const int ut = bid & 31, q = bid >> 5;
    const int u0 = ut * 4, b0 = q * 64;            // LSTM slice: 4 units x 64 rows

    for (int t = 0; t < TSTEP; t++) {
        const int rp = t & 1, wp = rp ^ 1;

        // ================= LSTM: 4 layers ====================================
        for (int l = 0; l < NL; l++) {
            if (l == 0) waitcnt(&c_red, NB * t);
            else        waitcnt(&c_h[l - 1], NB * (t + 1));

            ull*   ws = (ull*)smraw;               // [8][258]  gate-pair chains
            float* xs = (float*)(ws + 8 * 258);    // [64][132]
            float* hs = xs + 64 * 132;             // [64][132]

            // stage weights (L2-resident, 16 KB)
            for (int j = tid; j < 8 * 256; j += NT) {
                int ci = j >> 8, k = j & 255;
                int ul = ci >> 1, ch = ci & 1;
                int g0 = (ch ? 256 : 0) + u0 + ul;
                const float* Ws = ((k < 128) ? W_ih : W_hh) + l * 512 * H;
                int kk = k & 127;
                ws[ci * 258 + k] = pkc(__ldg(&Ws[g0 * H + kk]), __ldg(&Ws[(g0 + 128) * H + kk]));
            }
            // stage activations
            if (l == 0) {
                for (int j = tid; j < 64 * H; j += NT) {
                    int bl = j >> 7, k = j & 127;
                    int tok = __ldcg(&g_prev[b0 + bl]);
                    xs[bl * 132 + k] = __ldg(&W_in[tok * H + k]) + __ldg(&b_in[k]);
                }
            } else {
                for (int j = tid; j < 64 * H; j += NT) {
                    int bl = j >> 7, k = j & 127;
                    xs[bl * 132 + k] = __ldcg(&g_h[wp][l - 1][b0 + bl][k]);
                }
            }
            for (int j = tid; j < 64 * H; j += NT) {
                int bl = j >> 7, k = j & 127;
                hs[bl * 132 + k] = __ldcg(&g_h[rp][l][b0 + bl][k]);
            }
            __syncthreads();

            if (tid < 512) {
                int bl = tid >> 3, ul = (tid >> 1) & 3, ch = tid & 1;
                const ull*   w  = ws + (ul * 2 + ch) * 258;
                const float* xv = xs + bl * 132;
                const float* hv = hs + bl * 132;
                ull acc = 0ull;
#pragma unroll 8
                for (int k = 0; k < 128; k += 2) {
                    float2 x2 = *(const float2*)(xv + k);
                    ulonglong2 w2 = *(const ulonglong2*)(w + k);
                    fma2(acc, pk2(x2.x), w2.x);
                    fma2(acc, pk2(x2.y), w2.y);
                }
#pragma unroll 8
                for (int k = 0; k < 128; k += 2) {
                    float2 h2 = *(const float2*)(hv + k);
                    ulonglong2 w2 = *(const ulonglong2*)(w + 128 + k);
                    fma2(acc, pk2(h2.x), w2.x);
                    fma2(acc, pk2(h2.y), w2.y);
                }
                float2 vv = upk(acc);
                int u = u0 + ul, b = b0 + bl;
                int gA = (ch ? 256 : 0) + u;
                float a0 = vv.x + __ldg(&b_ih[l * 512 + gA])       + __ldg(&b_hh[l * 512 + gA]);
                float a1 = vv.y + __ldg(&b_ih[l * 512 + gA + 128]) + __ldg(&b_hh[l * 512 + gA + 128]);
                float p0 = __shfl_xor_sync(0xffffffffu, a0, 1);
                float p1 = __shfl_xor_sync(0xffffffffu, a1, 1);
                if (ch == 0) {   // holds (i,f); partner gave (g,o)
                    float co = __ldcg(&g_c[rp][l][b][u]);
                    float cn = sigm(a1) * co + sigm(a0) * tanhf(p0);
                    float hn = sigm(p1) * tanhf(cn);
                    __stcg(&g_c[wp][l][b][u], cn);
                    __stcg(&g_h[wp][l][b][u], hn);
                }
            }
            bumpcnt(&c_h[l]);
        }

        // ================= emb (all 128 blocks: 64 rows x 4 e-cols) ==========
        {
            waitcnt(&c_h[NL - 1], NB * (t + 1));
            float* hsm = (float*)smraw;            // [64][132]
            float* Wts = hsm + 64 * 132;           // [4][128]
            int r0 = q * 64, e0 = ut * 4;
            for (int j = tid; j < 64 * H; j += NT) {
                int row = j >> 7, k = j & 127;
                hsm[row * 132 + k] = __ldcg(&g_h[wp][NL - 1][r0 + row][k]);
            }
            for (int j = tid; j < 4 * H; j += NT)
                Wts[j] = __ldg(&W_re[(e0 + (j >> 7)) * H + (j & 127)]);
            __syncthreads();
            if (tid < 256) {
                int row = tid & 63, e = tid >> 6;
                const float* hv = hsm + row * 132;
                const float* wv = Wts + e * 128;
                float acc = 0.f;
#pragma unroll 8
                for (int k = 0; k < 128; k += 4) {
                    float4 h4 = *(const float4*)(hv + k);
                    float4 w4 = *(const float4*)(wv + k);
                    acc = fmaf(h4.x, w4.x, acc); acc = fmaf(h4.y, w4.y, acc);
                    acc = fmaf(h4.z, w4.z, acc); acc = fmaf(h4.w, w4.w, acc);
                }
                __stcg(&g_embT[(e0 + e) * BATCH + r0 + row], acc + __ldg(&b_re[e0 + e]));
            }
            bumpcnt(&c_emb);
        }

        // ================= logits -> g_scr ===================================
        waitcnt(&c_emb, NB * (t + 1));
        waitcnt(&c_norm, NB * t);                  // scratch free
        {
            float* Wp = (float*)smraw;             // [128k][132] W_lo tile (transposed)
            ull*   ep = (ull*)(smraw + 67584);     // [128k][132] emb batch-pairs
            // stage emb pairs once per step (straight copy: g_embT is pair layout)
            const ull* embp = (const ull*)g_embT;
            for (int j = tid; j < 128 * 128; j += NT) {
                int k = j >> 7, bp = j & 127;
                ep[k * 132 + bp] = __ldcg(&embp[k * 128 + bp]);
            }
            const int vq = tid & 31;               // 4 v each
            const int bg = (tid >> 5) & 15;        // 4 b-pairs each
            const int ph = tid >> 9;               // batch half
            const int bp0 = ph * 64 + bg * 4;

            for (int tt = bid; tt < NVT; tt += NB) {
                int v0 = tt * 128;
                __syncthreads();
                for (int j = tid; j < 128 * 128; j += NT) {
                    int vl = j >> 7, k = j & 127;
                    Wp[k * 132 + vl] = __ldg(&W_lo[(size_t)(v0 + vl) * H + k]);
                }
                __syncthreads();

                ull a00 = 0, a01 = 0, a02 = 0, a03 = 0;
                ull a10 = 0, a11 = 0, a12 = 0, a13 = 0;
                ull a20 = 0, a21 = 0, a22 = 0, a23 = 0;
                ull a30 = 0, a31 = 0, a32 = 0, a33 = 0;
                const float* wp_ = Wp + 4 * vq;
                const ull*   ep_ = ep + bp0;
#pragma unroll 2
                for (int k = 0; k < H; k++, wp_ += 132, ep_ += 132) {
                    float4 wv = *(const float4*)wp_;              // conflict-free LDS.128
                    ulonglong2 eA = *(const ulonglong2*)ep_;      // broadcast LDS.128
                    ulonglong2 eB = *(const ulonglong2*)(ep_ + 2);
                    ull w0 = pk2(wv.x), w1 = pk2(wv.y), w2r = pk2(wv.z), w3 = pk2(wv.w);
                    fma2(a00, w0, eA.x); fma2(a10, w1, eA.x); fma2(a20, w2r, eA.x); fma2(a30, w3, eA.x);
                    fma2(a01, w0, eA.y); fma2(a11, w1, eA.y); fma2(a21, w2r, eA.y); fma2(a31, w3, eA.y);
                    fma2(a02, w0, eB.x); fma2(a12, w1, eB.x); fma2(a22, w2r, eB.x); fma2(a32, w3, eB.x);
                    fma2(a03, w0, eB.y); fma2(a13, w1, eB.y); fma2(a23, w2r, eB.y); fma2(a33, w3, eB.y);
                }
                int v = v0 + 4 * vq;
                float4 bl4 = *(const float4*)(b_lo + v);
#pragma unroll
                for (int j = 0; j < 4; j++) {
                    ull u0v = (j == 0) ? a00 : (j == 1) ? a01 : (j == 2) ? a02 : a03;
                    ull u1v = (j == 0) ? a10 : (j == 1) ? a11 : (j == 2) ? a12 : a13;
                    ull u2v = (j == 0) ? a20 : (j == 1) ? a21 : (j == 2) ? a22 : a23;
                    ull u3v = (j == 0) ? a30 : (j == 1) ? a31 : (j == 2) ? a32 : a33;
                    float2 r0 = upk(u0v), r1 = upk(u1v), r2 = upk(u2v), r3 = upk(u3v);
                    int row = 2 * (bp0 + j);
                    float4 o0 = { r0.x + bl4.x, r1.x + bl4.y, r2.x + bl4.z, r3.x + bl4.w };
                    float4 o1 = { r0.y + bl4.x, r1.y + bl4.y, r2.y + bl4.z, r3.y + bl4.w };
                    __stcg((float4*)&g_scr[row][v],     o0);
                    __stcg((float4*)&g_scr[row + 1][v], o1);
                }
            }
        }
        bumpcnt(&c_log);

        // ====== softmax: reduce + argmax, then normalize (2 rows/block) ======
        waitcnt(&c_log, NB * (t + 1));
        {
            float* mS = (float*)smraw;
            float* sS = mS + 1024;
            int*   iS = (int*)(sS + 1024);
            int half = tid >> 9, lane = tid & 511;
            int r = 2 * bid + half;
            float m = -1e30f, s = 0.f; int idx = V;
            for (int v = lane; v < V; v += 512) {
                float lv = __ldcg(&g_scr[r][v]);
                if (lv > m) { s = s * __expf(m - lv) + 1.f; m = lv; idx = v; }
                else        { s += __expf(lv - m); }
            }
            mS[tid] = m; sS[tid] = s; iS[tid] = idx;
            __syncthreads();
            for (int off = 256; off > 0; off >>= 1) {
                if (lane < off) {
                    float m1 = mS[tid], m2 = mS[tid + off];
                    float s1 = sS[tid], s2 = sS[tid + off];
                    int   i1 = iS[tid], i2 = iS[tid + off];
                    float M = fmaxf(m1, m2);
                    sS[tid] = s1 * __expf(m1 - M) + s2 * __expf(m2 - M);
                    mS[tid] = M;
                    iS[tid] = (m1 > m2) ? i1 : ((m2 > m1) ? i2 : min(i1, i2));
                }
                __syncthreads();
            }
            float M   = mS[half << 9];
            float inv = 1.f / sS[half << 9];
            if (lane == 0) __stcg(&g_prev[r], iS[half << 9]);
            bumpcnt(&c_red);    // unblock step t+1 LSTM; norm below overlaps it
            float* orow = out + ((size_t)t * BATCH + r) * V;
            for (int v = lane; v < V; v += 512) {
                float lv = __ldcg(&g_scr[r][v]);
                __stcs(&orow[v], __expf(lv - M) * inv);
            }
        }
        bumpcnt(&c_norm);
    }

    // ---- reset counters for graph replay ----
    __syncthreads();
    if (tid == 0) {
        __threadfence();
        atomicAdd(&c_done, 1);
        if (bid == 0) {
            volatile int* vd = (volatile int*)&c_done;
            while (*vd < NB) __nanosleep(64);
            c_init = 0; c_emb = 0; c_log = 0; c_red = 0; c_norm = 0;
            for (int l = 0; l < NL; l++) c_h[l] = 0;
            __threadfence();
            *(volatile int*)&c_done = 0;
        }
    }
}

// ---------------- launch ----------------
extern "C" void kernel_launch(void* const* d_in, const int* in_sizes, int n_in,
                              void* d_out, int out_size) {
    const float* hidden = (const float*)d_in[0];
    const float* cell   = (const float*)d_in[1];
    const float* W_in   = (const float*)d_in[2];
    const float* b_in   = (const float*)d_in[3];
    const float* W_ih   = (const float*)d_in[4];
    const float* W_hh   = (const float*)d_in[5];
    const float* b_ih   = (const float*)d_in[6];
    const float* b_hh   = (const float*)d_in[7];
    const float* W_re   = (const float*)d_in[8];
    const float* b_re   = (const float*)d_in[9];
    const float* W_lo   = (const float*)d_in[10];
    const float* b_lo   = (const float*)d_in[11];
    const int*   eos    = (const int*)d_in[12];
    float* out = (float*)d_out;

    const int SMEM = 67584 + 128 * 132 * 8;   // 202752 B
    cudaFuncSetAttribute(decoder_kernel, cudaFuncAttributeMaxDynamicSharedMemorySize, SMEM);

    decoder_kernel<<<NB, NT, SMEM>>>(hidden, cell, W_in, b_in, W_ih, W_hh,
                                     b_ih, b_hh, W_re, b_re, W_lo, b_lo, eos, out);
}

// round 8
// speedup vs baseline: 2.0192x; 1.3499x over previous
#include <cuda_runtime.h>
#include <cuda_bf16.h>
#include <math.h>

#define BATCH 256
#define H     128
#define NL    4
#define V     32000
#define TSTEP 32
#define NB    128
#define NT    1024
#define NUNIT 250          // v-tiles of 128, M=256 each

typedef unsigned long long ull;

// ---------------- device scratch ----------------
__device__ __align__(16) float g_h[2][NL][BATCH][H];
__device__ __align__(16) float g_c[2][NL][BATCH][H];
__device__ __align__(16) __nv_bfloat16 g_ehi[BATCH * H];
__device__ __align__(16) __nv_bfloat16 g_elo[BATCH * H];
__device__ __align__(16) __nv_bfloat16 g_Whi[V * H];
__device__ __align__(16) __nv_bfloat16 g_Wlo2[V * H];
__device__ __align__(16) float g_scr[BATCH][V];      // logits scratch, L2-resident
__device__ int g_prev[BATCH];
__device__ int c_init, c_h[NL], c_emb, c_log, c_red, c_norm, c_done;

// ---------------- packed f32x2 helpers (LSTM) ----------------
__device__ __forceinline__ ull pk2(float x) {
    ull r; asm("mov.b64 %0, {%1, %1};" : "=l"(r) : "f"(x)); return r;
}
__device__ __forceinline__ ull pkc(float a, float b) {
    ull r; asm("mov.b64 %0, {%1, %2};" : "=l"(r) : "f"(a), "f"(b)); return r;
}
__device__ __forceinline__ void fma2(ull &acc, ull a, ull b) {
    asm("fma.rn.f32x2 %0, %1, %2, %3;" : "=l"(acc) : "l"(a), "l"(b), "l"(acc));
}
__device__ __forceinline__ float2 upk(ull v) {
    float2 r; asm("mov.b64 {%0, %1}, %2;" : "=f"(r.x), "=f"(r.y) : "l"(v)); return r;
}
__device__ __forceinline__ float sigm(float x) { return 1.0f / (1.0f + expf(-x)); }

// ---------------- dataflow sync ----------------
__device__ __forceinline__ void waitcnt(int* c, int target) {
    if (threadIdx.x == 0) {
        volatile int* vc = (volatile int*)c;
        while (*vc < target) __nanosleep(64);
        __threadfence();
    }
    __syncthreads();
}
__device__ __forceinline__ void bumpcnt(int* c) {
    __syncthreads();
    if (threadIdx.x == 0) { __threadfence(); atomicAdd(c, 1); }
}

// ---------------- mma.sync / ldmatrix (baseline PTX, runs on tensor cores) ---
__device__ __forceinline__ void ldmx4(unsigned &r0, unsigned &r1, unsigned &r2,
                                      unsigned &r3, unsigned addr) {
    asm volatile("ldmatrix.sync.aligned.m8n8.x4.shared.b16 {%0,%1,%2,%3}, [%4];"
                 : "=r"(r0), "=r"(r1), "=r"(r2), "=r"(r3) : "r"(addr));
}
__device__ __forceinline__ void mma_bf16(float* c, const unsigned* a, const unsigned* b) {
    asm volatile("mma.sync.aligned.m16n8k16.row.col.f32.bf16.bf16.f32 "
                 "{%0,%1,%2,%3}, {%4,%5,%6,%7}, {%8,%9}, {%0,%1,%2,%3};"
                 : "+f"(c[0]), "+f"(c[1]), "+f"(c[2]), "+f"(c[3])
                 : "r"(a[0]), "r"(a[1]), "r"(a[2]), "r"(a[3]), "r"(b[0]), "r"(b[1]));
}

// smem layout (bytes, dynamic):
//   logits: A_hi [256 x 272B] | A_lo | B_hi [128 x 272B] | B_lo   (pitch 272 = 136 bf16:
//           16B-aligned rows, bank offset 4/row -> ldmatrix conflict-free)
//   lstm:   ws(16512) | xs/hs(67584)  at +1024
#define SA_HI  1024
#define SA_LO  (SA_HI + 69632)
#define SB_HI  (SA_LO + 69632)
#define SB_LO  (SB_HI + 34816)
#define SMEM_BYTES (SB_LO + 34816)      // 209920

// ============================================================================
__global__ void __launch_bounds__(NT, 1)
decoder_kernel(const float* __restrict__ hidden, const float* __restrict__ cell,
               const float* __restrict__ W_in,  const float* __restrict__ b_in,
               const float* __restrict__ W_ih,  const float* __restrict__ W_hh,
               const float* __restrict__ b_ih,  const float* __restrict__ b_hh,
               const float* __restrict__ W_re,  const float* __restrict__ b_re,
               const float* __restrict__ W_lo,  const float* __restrict__ b_lo,
               const int*   __restrict__ eos,
               float* __restrict__ out)
{
    extern __shared__ char smraw[];
    unsigned smem_base;
    asm("{ .reg .u64 t; cvta.to.shared.u64 t, %1; cvt.u32.u64 %0, t; }"
        : "=r"(smem_base) : "l"(smraw));
    const int tid = threadIdx.x;
    const int bid = blockIdx.x;

    // ---- init: state copy + W_lo -> split bf16 (once per launch) ----
    {
        int j = bid * NT + tid;                 // NL*BATCH*H = 131072
        __stcg(&(&g_h[0][0][0][0])[j], hidden[j]);
        __stcg(&(&g_c[0][0][0][0])[j], cell[j]);
        if (bid == 0 && tid < BATCH) __stcg(&g_prev[tid], __ldg(&eos[0]));
        for (int i = bid * NT + tid; i < V * H; i += NB * NT) {
            float w = __ldg(&W_lo[i]);
            __nv_bfloat16 hi = __float2bfloat16(w);
            g_Whi[i]  = hi;
            g_Wlo2[i] = __float2bfloat16(w - __bfloat162float(hi));
        }
    }
    bumpcnt(&c_init);
    waitcnt(&c_init, NB);

    const int ut = bid & 31, q = bid >> 5;
    const int u0 = ut * 4, b0 = q * 64;        // LSTM slice: 4 units x 64 rows

    for (int t = 0; t < TSTEP; t++) {
        const int rp = t & 1, wp = rp ^ 1;

        // ================= LSTM: 4 layers ====================================
        for (int l = 0; l < NL; l++) {
            if (l == 0) waitcnt(&c_red, NB * t);
            else        waitcnt(&c_h[l - 1], NB * (t + 1));

            ull*   ws = (ull*)(smraw + 1024);      // [8][258]
            float* xs = (float*)(ws + 8 * 258);    // [64][132]
            float* hs = xs + 64 * 132;             // [64][132]

            for (int j = tid; j < 8 * 256; j += NT) {
                int ci = j >> 8, k = j & 255;
                int ul = ci >> 1, ch = ci & 1;
                int g0 = (ch ? 256 : 0) + u0 + ul;
                const float* Ws = ((k < 128) ? W_ih : W_hh) + l * 512 * H;
                int kk = k & 127;
                ws[ci * 258 + k] = pkc(__ldg(&Ws[g0 * H + kk]), __ldg(&Ws[(g0 + 128) * H + kk]));
            }
            if (l == 0) {
                for (int j = tid; j < 64 * H; j += NT) {
                    int bl = j >> 7, k = j & 127;
                    int tok = __ldcg(&g_prev[b0 + bl]);
                    xs[bl * 132 + k] = __ldg(&W_in[tok * H + k]) + __ldg(&b_in[k]);
                }
            } else {
                for (int j = tid; j < 64 * H; j += NT) {
                    int bl = j >> 7, k = j & 127;
                    xs[bl * 132 + k] = __ldcg(&g_h[wp][l - 1][b0 + bl][k]);
                }
            }
            for (int j = tid; j < 64 * H; j += NT) {
                int bl = j >> 7, k = j & 127;
                hs[bl * 132 + k] = __ldcg(&g_h[rp][l][b0 + bl][k]);
            }
            __syncthreads();

            if (tid < 512) {
                int bl = tid >> 3, ul = (tid >> 1) & 3, ch = tid & 1;
                const ull*   w  = ws + (ul * 2 + ch) * 258;
                const float* xv = xs + bl * 132;
                const float* hv = hs + bl * 132;
                ull acc = 0ull;
#pragma unroll 8
                for (int k = 0; k < 128; k += 2) {
                    float2 x2 = *(const float2*)(xv + k);
                    ulonglong2 w2 = *(const ulonglong2*)(w + k);
                    fma2(acc, pk2(x2.x), w2.x);
                    fma2(acc, pk2(x2.y), w2.y);
                }
#pragma unroll 8
                for (int k = 0; k < 128; k += 2) {
                    float2 h2 = *(const float2*)(hv + k);
                    ulonglong2 w2 = *(const ulonglong2*)(w + 128 + k);
                    fma2(acc, pk2(h2.x), w2.x);
                    fma2(acc, pk2(h2.y), w2.y);
                }
                float2 vv = upk(acc);
                int u = u0 + ul, b = b0 + bl;
                int gA = (ch ? 256 : 0) + u;
                float a0 = vv.x + __ldg(&b_ih[l * 512 + gA])       + __ldg(&b_hh[l * 512 + gA]);
                float a1 = vv.y + __ldg(&b_ih[l * 512 + gA + 128]) + __ldg(&b_hh[l * 512 + gA + 128]);
                float p0 = __shfl_xor_sync(0xffffffffu, a0, 1);
                float p1 = __shfl_xor_sync(0xffffffffu, a1, 1);
                if (ch == 0) {
                    float co = __ldcg(&g_c[rp][l][b][u]);
                    float cn = sigm(a1) * co + sigm(a0) * tanhf(p0);
                    float hn = sigm(p1) * tanhf(cn);
                    __stcg(&g_c[wp][l][b][u], cn);
                    __stcg(&g_h[wp][l][b][u], hn);
                }
            }
            bumpcnt(&c_h[l]);
        }

        // ================= emb: fp32 + bf16 hi/lo split ======================
        {
            waitcnt(&c_h[NL - 1], NB * (t + 1));
            float* hsm = (float*)(smraw + 1024);   // [64][132]
            float* Wts = hsm + 64 * 132;           // [4][128]
            int r0 = q * 64, e0 = ut * 4;
            for (int j = tid; j < 64 * H; j += NT) {
                int row = j >> 7, k = j & 127;
                hsm[row * 132 + k] = __ldcg(&g_h[wp][NL - 1][r0 + row][k]);
            }
            for (int j = tid; j < 4 * H; j += NT)
                Wts[j] = __ldg(&W_re[(e0 + (j >> 7)) * H + (j & 127)]);
            __syncthreads();
            if (tid < 256) {
                int row = tid & 63, e = tid >> 6;
                const float* hv = hsm + row * 132;
                const float* wv = Wts + e * 128;
                float acc = 0.f;
#pragma unroll 8
                for (int k = 0; k < 128; k += 4) {
                    float4 h4 = *(const float4*)(hv + k);
                    float4 w4 = *(const float4*)(wv + k);
                    acc = fmaf(h4.x, w4.x, acc); acc = fmaf(h4.y, w4.y, acc);
                    acc = fmaf(h4.z, w4.z, acc); acc = fmaf(h4.w, w4.w, acc);
                }
                float ev = acc + __ldg(&b_re[e0 + e]);
                __nv_bfloat16 hi = __float2bfloat16(ev);
                int idx = (r0 + row) * H + e0 + e;
                g_ehi[idx] = hi;
                g_elo[idx] = __float2bfloat16(ev - __bfloat162float(hi));
            }
            bumpcnt(&c_emb);
        }

        // ================= logits: split-bf16 mma.sync =======================
        waitcnt(&c_emb, NB * (t + 1));
        waitcnt(&c_norm, NB * t);
        {
            // stage A (emb hi/lo): 256 rows x 128 k bf16, pitch 272 B
            {
                const uint4* eh = (const uint4*)g_ehi;
                const uint4* el = (const uint4*)g_elo;
                for (int j = tid; j < 4096; j += NT) {
                    int r = j >> 4, kq = j & 15;
                    *(uint4*)(smraw + SA_HI + r * 272 + kq * 16) = __ldcg(&eh[j]);
                    *(uint4*)(smraw + SA_LO + r * 272 + kq * 16) = __ldcg(&el[j]);
                }
            }
            const int lane = tid & 31, wid = tid >> 5;
            const int m_base = (wid >> 2) * 32;
            const int n_base = (wid & 3) * 32;
            const int arow  = lane & 15;
            const int ahoff = ((lane >> 4) & 1) * 16;                 // k-half bytes
            const int nrow  = (lane & 7) + ((lane & 16) >> 1);
            const int bhoff = ((lane >> 3) & 1) * 16;
            const int qrow = lane >> 2, qcol = (lane & 3) * 2;

            for (int u = bid; u < NUNIT; u += NB) {
                int v0 = u * 128;
                __syncthreads();   // prev unit's mma done before B restage
                {
                    const uint4* wh = (const uint4*)g_Whi;
                    const uint4* wl = (const uint4*)g_Wlo2;
                    int sb = v0 * 16;   // 16 uint4 per row
                    for (int j = tid; j < 2048; j += NT) {
                        int r = j >> 4, kq = j & 15;
                        *(uint4*)(smraw + SB_HI + r * 272 + kq * 16) = __ldg(&wh[sb + j]);
                        *(uint4*)(smraw + SB_LO + r * 272 + kq * 16) = __ldg(&wl[sb + j]);
                    }
                }
                __syncthreads();

                float c[2][4][4];
#pragma unroll
                for (int mi = 0; mi < 2; mi++)
#pragma unroll
                    for (int n8 = 0; n8 < 4; n8++)
#pragma unroll
                        for (int e = 0; e < 4; e++) c[mi][n8][e] = 0.f;

#pragma unroll 1
                for (int p = 0; p < 3; p++) {
                    unsigned Ab = smem_base + ((p == 2) ? SA_LO : SA_HI);
                    unsigned Bb = smem_base + ((p == 1) ? SB_LO : SB_HI);
                    unsigned a_r0 = Ab + (unsigned)(m_base + arow) * 272 + ahoff;
                    unsigned b_r0 = Bb + (unsigned)(n_base + nrow) * 272 + bhoff;
#pragma unroll 2
                    for (int ks = 0; ks < 8; ks++) {
                        unsigned koff = ks * 32;
                        unsigned a[2][4], bb[4][2];
                        ldmx4(a[0][0], a[0][1], a[0][2], a[0][3], a_r0 + koff);
                        ldmx4(a[1][0], a[1][1], a[1][2], a[1][3], a_r0 + 16 * 272 + koff);
                        ldmx4(bb[0][0], bb[0][1], bb[1][0], bb[1][1], b_r0 + koff);
                        ldmx4(bb[2][0], bb[2][1], bb[3][0], bb[3][1], b_r0 + 16 * 272 + koff);
#pragma unroll
                        for (int mi = 0; mi < 2; mi++)
#pragma unroll
                            for (int n8 = 0; n8 < 4; n8++)
                                mma_bf16(c[mi][n8], a[mi], bb[n8]);
                    }
                }

                // epilogue: + b_lo, store to g_scr
#pragma unroll
                for (int mi = 0; mi < 2; mi++) {
                    int r = m_base + mi * 16 + qrow;
#pragma unroll
                    for (int n8 = 0; n8 < 4; n8++) {
                        int v = v0 + n_base + n8 * 8 + qcol;
                        float2 bl = *(const float2*)(b_lo + v);
                        float2 o0 = { c[mi][n8][0] + bl.x, c[mi][n8][1] + bl.y };
                        float2 o1 = { c[mi][n8][2] + bl.x, c[mi][n8][3] + bl.y };
                        __stcg((float2*)&g_scr[r][v],     o0);
                        __stcg((float2*)&g_scr[r + 8][v], o1);
                    }
                }
            }
        }
        bumpcnt(&c_log);

        // ====== softmax: reduce + argmax, then normalize (2 rows/block) ======
        waitcnt(&c_log, NB * (t + 1));
        {
            float* mS = (float*)(smraw + 1024);
            float* sS = mS + 1024;
            int*   iS = (int*)(sS + 1024);
            int half = tid >> 9, lane = tid & 511;
            int r = 2 * bid + half;
            float m = -1e30f, s = 0.f; int idx = V;
            for (int v = lane; v < V; v += 512) {
                float lv = __ldcg(&g_scr[r][v]);
                if (lv > m) { s = s * __expf(m - lv) + 1.f; m = lv; idx = v; }
                else        { s += __expf(lv - m); }
            }
            mS[tid] = m; sS[tid] = s; iS[tid] = idx;
            __syncthreads();
            for (int off = 256; off > 0; off >>= 1) {
                if (lane < off) {
                    float m1 = mS[tid], m2 = mS[tid + off];
                    float s1 = sS[tid], s2 = sS[tid + off];
                    int   i1 = iS[tid], i2 = iS[tid + off];
                    float M = fmaxf(m1, m2);
                    sS[tid] = s1 * __expf(m1 - M) + s2 * __expf(m2 - M);
                    mS[tid] = M;
                    iS[tid] = (m1 > m2) ? i1 : ((m2 > m1) ? i2 : min(i1, i2));
                }
                __syncthreads();
            }
            float M   = mS[half << 9];
            float inv = 1.f / sS[half << 9];
            if (lane == 0) __stcg(&g_prev[r], iS[half << 9]);
            bumpcnt(&c_red);
            float* orow = out + ((size_t)t * BATCH + r) * V;
            for (int v = lane; v < V; v += 512) {
                float lv = __ldcg(&g_scr[r][v]);
                __stcs(&orow[v], __expf(lv - M) * inv);
            }
        }
        bumpcnt(&c_norm);
    }

    // ---- reset counters for graph replay ----
    __syncthreads();
    if (tid == 0) {
        __threadfence();
        atomicAdd(&c_done, 1);
        if (bid == 0) {
            volatile int* vd = (volatile int*)&c_done;
            while (*vd < NB) __nanosleep(64);
            c_init = 0; c_emb = 0; c_log = 0; c_red = 0; c_norm = 0;
            for (int l = 0; l < NL; l++) c_h[l] = 0;
            __threadfence();
            *(volatile int*)&c_done = 0;
        }
    }
}

// ---------------- launch ----------------
extern "C" void kernel_launch(void* const* d_in, const int* in_sizes, int n_in,
                              void* d_out, int out_size) {
    const float* hidden = (const float*)d_in[0];
    const float* cell   = (const float*)d_in[1];
    const float* W_in   = (const float*)d_in[2];
    const float* b_in   = (const float*)d_in[3];
    const float* W_ih   = (const float*)d_in[4];
    const float* W_hh   = (const float*)d_in[5];
    const float* b_ih   = (const float*)d_in[6];
    const float* b_hh   = (const float*)d_in[7];
    const float* W_re   = (const float*)d_in[8];
    const float* b_re   = (const float*)d_in[9];
    const float* W_lo   = (const float*)d_in[10];
    const float* b_lo   = (const float*)d_in[11];
    const int*   eos    = (const int*)d_in[12];
    float* out = (float*)d_out;

    cudaFuncSetAttribute(decoder_kernel, cudaFuncAttributeMaxDynamicSharedMemorySize, SMEM_BYTES);
    decoder_kernel<<<NB, NT, SMEM_BYTES>>>(hidden, cell, W_in, b_in, W_ih, W_hh,
                                           b_ih, b_hh, W_re, b_re, W_lo, b_lo, eos, out);
}

// round 9
// speedup vs baseline: 2.2441x; 1.1114x over previous
#include <cuda_runtime.h>
#include <cuda_bf16.h>
#include <math.h>

#define BATCH 256
#define H     128
#define NL    4
#define V     32000
#define TSTEP 32
#define NB    128
#define NT    1024
#define NUNIT 250          // v-tiles of 128, M=256 each

typedef unsigned long long ull;

// ---------------- device scratch ----------------
__device__ __align__(16) float g_h[2][NL][BATCH][H];
__device__ __align__(16) float g_c[2][NL][BATCH][H];
__device__ __align__(16) __nv_bfloat16 g_ehi[BATCH * H];
__device__ __align__(16) __nv_bfloat16 g_elo[BATCH * H];
__device__ __align__(16) __nv_bfloat16 g_Whi[V * H];
__device__ __align__(16) __nv_bfloat16 g_Wlo2[V * H];
__device__ __align__(16) float g_scr[BATCH][V];      // exp values, L2-resident
__device__ ull g_amax[2][BATCH];                     // packed (max,argmax) keys per parity
__device__ int g_prev[BATCH];
__device__ unsigned g_mw2key, g_mbkey;               // ordered-float atomic max keys
__device__ float g_embB;                             // sum_e (L1 bound_e)^2
__device__ int c_init, c_emb, c_log, c_norm, c_done;
__device__ int c_hq[NL][4][32];                      // per-quarter LSTM layer counters
__device__ int c_redq[4][32];                        // per-quarter feedback counters

// ---------------- packed f32x2 helpers (LSTM) ----------------
__device__ __forceinline__ ull pk2(float x) {
    ull r; asm("mov.b64 %0, {%1, %1};" : "=l"(r) : "f"(x)); return r;
}
__device__ __forceinline__ ull pkc(float a, float b) {
    ull r; asm("mov.b64 %0, {%1, %2};" : "=l"(r) : "f"(a), "f"(b)); return r;
}
__device__ __forceinline__ void fma2(ull &acc, ull a, ull b) {
    asm("fma.rn.f32x2 %0, %1, %2, %3;" : "=l"(acc) : "l"(a), "l"(b), "l"(acc));
}
__device__ __forceinline__ float2 upk(ull v) {
    float2 r; asm("mov.b64 {%0, %1}, %2;" : "=f"(r.x), "=f"(r.y) : "l"(v)); return r;
}
__device__ __forceinline__ float sigm(float x) { return 1.0f / (1.0f + expf(-x)); }

// ordered-float <-> uint (monotone)
__device__ __forceinline__ unsigned ordk(float f) {
    unsigned u = __float_as_uint(f);
    return (u & 0x80000000u) ? ~u : (u | 0x80000000u);
}
__device__ __forceinline__ ull mkkey(float o, int v) {
    return ((ull)ordk(o) << 32) | (ull)(0xffffffffu - (unsigned)v);
}
__device__ __forceinline__ float keyf(unsigned k) {
    return __uint_as_float((k & 0x80000000u) ? (k & 0x7fffffffu) : ~k);
}

// ---------------- dataflow sync ----------------
__device__ __forceinline__ void waitcnt(int* c, int target) {
    if (threadIdx.x == 0) {
        volatile int* vc = (volatile int*)c;
        while (*vc < target) __nanosleep(64);
        __threadfence();
    }
    __syncthreads();
}
__device__ __forceinline__ void bumpcnt(int* c) {
    __syncthreads();
    if (threadIdx.x == 0) { __threadfence(); atomicAdd(c, 1); }
}

// ---------------- mma.sync / ldmatrix ----------------
__device__ __forceinline__ void ldmx4(unsigned &r0, unsigned &r1, unsigned &r2,
                                      unsigned &r3, unsigned addr) {
    asm volatile("ldmatrix.sync.aligned.m8n8.x4.shared.b16 {%0,%1,%2,%3}, [%4];"
                 : "=r"(r0), "=r"(r1), "=r"(r2), "=r"(r3) : "r"(addr));
}
__device__ __forceinline__ void mma_bf16(float* c, const unsigned* a, const unsigned* b) {
    asm volatile("mma.sync.aligned.m16n8k16.row.col.f32.bf16.bf16.f32 "
                 "{%0,%1,%2,%3}, {%4,%5,%6,%7}, {%8,%9}, {%0,%1,%2,%3};"
                 : "+f"(c[0]), "+f"(c[1]), "+f"(c[2]), "+f"(c[3])
                 : "r"(a[0]), "r"(a[1]), "r"(a[2]), "r"(a[3]), "r"(b[0]), "r"(b[1]));
}

// smem layout (bytes): A_hi/A_lo [256 x 272B], B_hi/B_lo [128 x 272B], keys [256][4] ull
#define SA_HI  1024
#define SA_LO  (SA_HI + 69632)
#define SB_HI  (SA_LO + 69632)
#define SB_LO  (SB_HI + 34816)
#define SM_KEY (SB_LO + 34816)
#define SMEM_BYTES (SM_KEY + 8192)      // 218112

// ============================================================================
__global__ void __launch_bounds__(NT, 1)
decoder_kernel(const float* __restrict__ hidden, const float* __restrict__ cell,
               const float* __restrict__ W_in,  const float* __restrict__ b_in,
               const float* __restrict__ W_ih,  const float* __restrict__ W_hh,
               const float* __restrict__ b_ih,  const float* __restrict__ b_hh,
               const float* __restrict__ W_re,  const float* __restrict__ b_re,
               const float* __restrict__ W_lo,  const float* __restrict__ b_lo,
               const int*   __restrict__ eos,
               float* __restrict__ out)
{
    extern __shared__ char smraw[];
    unsigned smem_base;
    asm("{ .reg .u64 t; cvta.to.shared.u64 t, %1; cvt.u32.u64 %0, t; }"
        : "=r"(smem_base) : "l"(smraw));
    const int tid = threadIdx.x;
    const int bid = blockIdx.x;

    // ---- init: state copy + W_lo row-wise split + norm bounds ----
    {
        int j = bid * NT + tid;                 // NL*BATCH*H = 131072
        __stcg(&(&g_h[0][0][0][0])[j], hidden[j]);
        __stcg(&(&g_c[0][0][0][0])[j], cell[j]);
        if (bid == 0 && tid < BATCH) __stcg(&g_prev[tid], __ldg(&eos[0]));
        if (bid == 0 && tid < 2 * BATCH) ((ull*)g_amax)[tid] = 0ull;

        int v = bid * NT + tid;                 // one row per thread (v < 32000)
        if (v < V) {
            const float4* wr = (const float4*)(W_lo + (size_t)v * H);
            uint4* oh = (uint4*)(g_Whi  + (size_t)v * H);
            uint4* ol = (uint4*)(g_Wlo2 + (size_t)v * H);
            float nrm = 0.f;
#pragma unroll 4
            for (int jq = 0; jq < 16; jq++) {
                float4 a = __ldg(&wr[2 * jq]);
                float4 b2 = __ldg(&wr[2 * jq + 1]);
                float w8[8] = {a.x, a.y, a.z, a.w, b2.x, b2.y, b2.z, b2.w};
                unsigned hh[4], llp[4];
#pragma unroll
                for (int p = 0; p < 4; p++) {
                    __nv_bfloat16 h0 = __float2bfloat16(w8[2 * p]);
                    __nv_bfloat16 h1 = __float2bfloat16(w8[2 * p + 1]);
                    __nv_bfloat16 l0 = __float2bfloat16(w8[2 * p] - __bfloat162float(h0));
                    __nv_bfloat16 l1 = __float2bfloat16(w8[2 * p + 1] - __bfloat162float(h1));
                    hh[p]  = (unsigned)__bfloat16_as_ushort(h0) | ((unsigned)__bfloat16_as_ushort(h1) << 16);
                    llp[p] = (unsigned)__bfloat16_as_ushort(l0) | ((unsigned)__bfloat16_as_ushort(l1) << 16);
                    nrm += w8[2 * p] * w8[2 * p] + w8[2 * p + 1] * w8[2 * p + 1];
                }
                oh[jq] = make_uint4(hh[0], hh[1], hh[2], hh[3]);
                ol[jq] = make_uint4(llp[0], llp[1], llp[2], llp[3]);
            }
            atomicMax(&g_mw2key, ordk(nrm));
            atomicMax(&g_mbkey, ordk(fabsf(__ldg(&b_lo[v]))));
        }
        if (bid == 0) {                         // emb L1 bound (block 0)
            float* tmp = (float*)(smraw + SA_HI);
            if (tid < 128) {
                float s1 = 0.f;
                for (int k = 0; k < H; k++) s1 += fabsf(__ldg(&W_re[tid * H + k]));
                s1 += fabsf(__ldg(&b_re[tid]));
                tmp[tid] = s1 * s1;
            }
            __syncthreads();
            if (tid == 0) {
                float s = 0.f;
                for (int e = 0; e < 128; e++) s += tmp[e];
                g_embB = s;
            }
        }
    }
    bumpcnt(&c_init);
    waitcnt(&c_init, NB);

    const float Mhat = sqrtf(__ldcg(&g_embB)) * sqrtf(keyf(*(volatile unsigned*)&g_mw2key))
                     + keyf(*(volatile unsigned*)&g_mbkey);

    const int ut = bid & 31, q = bid >> 5;
    const int u0 = ut * 4, b0 = q * 64;        // LSTM slice: 4 units x 64 rows

    for (int t = 0; t < TSTEP; t++) {
        const int rp = t & 1, wp = rp ^ 1;

        // ================= LSTM: 4 layers (per-quarter sync) =================
        for (int l = 0; l < NL; l++) {
            if (l == 0) waitcnt(&c_redq[q][0], 32 * t);
            else        waitcnt(&c_hq[l - 1][q][0], 32 * (t + 1));

            ull*   ws = (ull*)(smraw + 1024);      // [8][258]
            float* xs = (float*)(ws + 8 * 258);    // [64][132]
            float* hs = xs + 64 * 132;             // [64][132]

            for (int j = tid; j < 8 * 256; j += NT) {
                int ci = j >> 8, k = j & 255;
                int ul = ci >> 1, ch = ci & 1;
                int g0 = (ch ? 256 : 0) + u0 + ul;
                const float* Ws = ((k < 128) ? W_ih : W_hh) + l * 512 * H;
                int kk = k & 127;
                ws[ci * 258 + k] = pkc(__ldg(&Ws[g0 * H + kk]), __ldg(&Ws[(g0 + 128) * H + kk]));
            }
            if (l == 0) {
                for (int j = tid; j < 64 * H; j += NT) {
                    int bl = j >> 7, k = j & 127;
                    int tok = __ldcg(&g_prev[b0 + bl]);
                    xs[bl * 132 + k] = __ldg(&W_in[tok * H + k]) + __ldg(&b_in[k]);
                }
            } else {
                for (int j = tid; j < 64 * H; j += NT) {
                    int bl = j >> 7, k = j & 127;
                    xs[bl * 132 + k] = __ldcg(&g_h[wp][l - 1][b0 + bl][k]);
                }
            }
            for (int j = tid; j < 64 * H; j += NT) {
                int bl = j >> 7, k = j & 127;
                hs[bl * 132 + k] = __ldcg(&g_h[rp][l][b0 + bl][k]);
            }
            __syncthreads();

            if (tid < 512) {
                int bl = tid >> 3, ul = (tid >> 1) & 3, ch = tid & 1;
                const ull*   w  = ws + (ul * 2 + ch) * 258;
                const float* xv = xs + bl * 132;
                const float* hv = hs + bl * 132;
                ull acc = 0ull;
#pragma unroll 8
                for (int k = 0; k < 128; k += 2) {
                    float2 x2 = *(const float2*)(xv + k);
                    ulonglong2 w2 = *(const ulonglong2*)(w + k);
                    fma2(acc, pk2(x2.x), w2.x);
                    fma2(acc, pk2(x2.y), w2.y);
                }
#pragma unroll 8
                for (int k = 0; k < 128; k += 2) {
                    float2 h2 = *(const float2*)(hv + k);
                    ulonglong2 w2 = *(const ulonglong2*)(w + 128 + k);
                    fma2(acc, pk2(h2.x), w2.x);
                    fma2(acc, pk2(h2.y), w2.y);
                }
                float2 vv = upk(acc);
                int u = u0 + ul, b = b0 + bl;
                int gA = (ch ? 256 : 0) + u;
                float a0 = vv.x + __ldg(&b_ih[l * 512 + gA])       + __ldg(&b_hh[l * 512 + gA]);
                float a1 = vv.y + __ldg(&b_ih[l * 512 + gA + 128]) + __ldg(&b_hh[l * 512 + gA + 128]);
                float p0 = __shfl_xor_sync(0xffffffffu, a0, 1);
                float p1 = __shfl_xor_sync(0xffffffffu, a1, 1);
                if (ch == 0) {
                    float co = __ldcg(&g_c[rp][l][b][u]);
                    float cn = sigm(a1) * co + sigm(a0) * tanhf(p0);
                    float hn = sigm(p1) * tanhf(cn);
                    __stcg(&g_c[wp][l][b][u], cn);
                    __stcg(&g_h[wp][l][b][u], hn);
                }
            }
            bumpcnt(&c_hq[l][q][0]);
        }

        // ================= emb: fp32 + bf16 hi/lo split ======================
        {
            waitcnt(&c_hq[NL - 1][q][0], 32 * (t + 1));
            float* hsm = (float*)(smraw + 1024);   // [64][132]
            float* Wts = hsm + 64 * 132;           // [4][128]
            int r0 = q * 64, e0 = ut * 4;
            for (int j = tid; j < 64 * H; j += NT) {
                int row = j >> 7, k = j & 127;
                hsm[row * 132 + k] = __ldcg(&g_h[wp][NL - 1][r0 + row][k]);
            }
            for (int j = tid; j < 4 * H; j += NT)
                Wts[j] = __ldg(&W_re[(e0 + (j >> 7)) * H + (j & 127)]);
            __syncthreads();
            if (tid < 256) {
                int row = tid & 63, e = tid >> 6;
                const float* hv = hsm + row * 132;
                const float* wv = Wts + e * 128;
                float acc = 0.f;
#pragma unroll 8
                for (int k = 0; k < 128; k += 4) {
                    float4 h4 = *(const float4*)(hv + k);
                    float4 w4 = *(const float4*)(wv + k);
                    acc = fmaf(h4.x, w4.x, acc); acc = fmaf(h4.y, w4.y, acc);
                    acc = fmaf(h4.z, w4.z, acc); acc = fmaf(h4.w, w4.w, acc);
                }
                float ev = acc + __ldg(&b_re[e0 + e]);
                __nv_bfloat16 hi = __float2bfloat16(ev);
                int idx = (r0 + row) * H + e0 + e;
                g_ehi[idx] = hi;
                g_elo[idx] = __float2bfloat16(ev - __bfloat162float(hi));
            }
            bumpcnt(&c_emb);
        }

        // ================= logits: split-bf16 mma.sync + exp epilogue ========
        waitcnt(&c_emb, NB * (t + 1));
        waitcnt(&c_norm, NB * t);
        {
            {   // stage A (emb hi/lo)
                const uint4* eh = (const uint4*)g_ehi;
                const uint4* el = (const uint4*)g_elo;
                for (int j = tid; j < 4096; j += NT) {
                    int r = j >> 4, kq = j & 15;
                    *(uint4*)(smraw + SA_HI + r * 272 + kq * 16) = __ldcg(&eh[j]);
                    *(uint4*)(smraw + SA_LO + r * 272 + kq * 16) = __ldcg(&el[j]);
                }
            }
            const int lane = tid & 31, wid = tid >> 5;
            const int m_base = (wid >> 2) * 32;
            const int n_base = (wid & 3) * 32;
            const int arow  = lane & 15;
            const int ahoff = ((lane >> 4) & 1) * 16;
            const int nrow  = (lane & 7) + ((lane & 16) >> 1);
            const int bhoff = ((lane >> 3) & 1) * 16;
            const int qrow = lane >> 2, qcol = (lane & 3) * 2;
            ull* keys = (ull*)(smraw + SM_KEY);    // [256][4]
            ull gbest = 0ull;

            for (int u = bid; u < NUNIT; u += NB) {
                int v0 = u * 128;
                {
                    const uint4* wh = (const uint4*)g_Whi;
                    const uint4* wl = (const uint4*)g_Wlo2;
                    int sb = v0 * 16;
                    for (int j = tid; j < 2048; j += NT) {
                        int r = j >> 4, kq = j & 15;
                        *(uint4*)(smraw + SB_HI + r * 272 + kq * 16) = __ldg(&wh[sb + j]);
                        *(uint4*)(smraw + SB_LO + r * 272 + kq * 16) = __ldg(&wl[sb + j]);
                    }
                }
                __syncthreads();

                float c[2][4][4];
#pragma unroll
                for (int mi = 0; mi < 2; mi++)
#pragma unroll
                    for (int n8 = 0; n8 < 4; n8++)
#pragma unroll
                        for (int e = 0; e < 4; e++) c[mi][n8][e] = 0.f;

#pragma unroll 1
                for (int p = 0; p < 3; p++) {
                    unsigned Ab = smem_base + ((p == 2) ? SA_LO : SA_HI);
                    unsigned Bb = smem_base + ((p == 1) ? SB_LO : SB_HI);
                    unsigned a_r0 = Ab + (unsigned)(m_base + arow) * 272 + ahoff;
                    unsigned b_r0 = Bb + (unsigned)(n_base + nrow) * 272 + bhoff;
#pragma unroll 2
                    for (int ks = 0; ks < 8; ks++) {
                        unsigned koff = ks * 32;
                        unsigned a[2][4], bb[4][2];
                        ldmx4(a[0][0], a[0][1], a[0][2], a[0][3], a_r0 + koff);
                        ldmx4(a[1][0], a[1][1], a[1][2], a[1][3], a_r0 + 16 * 272 + koff);
                        ldmx4(bb[0][0], bb[0][1], bb[1][0], bb[1][1], b_r0 + koff);
                        ldmx4(bb[2][0], bb[2][1], bb[3][0], bb[3][1], b_r0 + 16 * 272 + koff);
#pragma unroll
                        for (int mi = 0; mi < 2; mi++)
#pragma unroll
                            for (int n8 = 0; n8 < 4; n8++)
                                mma_bf16(c[mi][n8], a[mi], bb[n8]);
                    }
                }

                // epilogue: bias, per-row keys, exp, store e
                ull bk[2][2] = {{0ull, 0ull}, {0ull, 0ull}};
#pragma unroll
                for (int mi = 0; mi < 2; mi++) {
                    int r = m_base + mi * 16 + qrow;
#pragma unroll
                    for (int n8 = 0; n8 < 4; n8++) {
                        int v = v0 + n_base + n8 * 8 + qcol;
                        float2 bl = *(const float2*)(b_lo + v);
                        float o0 = c[mi][n8][0] + bl.x, o1 = c[mi][n8][1] + bl.y;
                        float o2 = c[mi][n8][2] + bl.x, o3 = c[mi][n8][3] + bl.y;
                        ull k0 = mkkey(o0, v), k1 = mkkey(o1, v + 1);
                        ull k2 = mkkey(o2, v), k3 = mkkey(o3, v + 1);
                        bk[mi][0] = max(bk[mi][0], max(k0, k1));
                        bk[mi][1] = max(bk[mi][1], max(k2, k3));
                        float2 e0 = { __expf(o0 - Mhat), __expf(o1 - Mhat) };
                        float2 e1 = { __expf(o2 - Mhat), __expf(o3 - Mhat) };
                        __stcg((float2*)&g_scr[r][v],     e0);
                        __stcg((float2*)&g_scr[r + 8][v], e1);
                    }
                }
#pragma unroll
                for (int mi = 0; mi < 2; mi++)
#pragma unroll
                    for (int hh = 0; hh < 2; hh++) {
                        ull k = bk[mi][hh];
                        k = max(k, __shfl_xor_sync(0xffffffffu, k, 1));
                        k = max(k, __shfl_xor_sync(0xffffffffu, k, 2));
                        bk[mi][hh] = k;
                    }
                if ((lane & 3) == 0) {
                    int nw = wid & 3;
#pragma unroll
                    for (int mi = 0; mi < 2; mi++)
#pragma unroll
                        for (int hh = 0; hh < 2; hh++)
                            keys[(m_base + mi * 16 + qrow + hh * 8) * 4 + nw] = bk[mi][hh];
                }
                __syncthreads();
                if (tid < 256) {
                    ull k = max(max(keys[tid * 4], keys[tid * 4 + 1]),
                                max(keys[tid * 4 + 2], keys[tid * 4 + 3]));
                    gbest = max(gbest, k);
                }
            }
            if (tid < 256 && gbest != 0ull)
                atomicMax(&g_amax[rp][tid], gbest);
        }
        bumpcnt(&c_log);

        // ====== softmax: sum pass + scale pass (2 rows/block) ================
        waitcnt(&c_log, NB * (t + 1));
        {
            float* sred = (float*)(smraw + 1024);  // [32]
            float* sInv = sred + 32;               // [2]
            int half = tid >> 9, lane9 = tid & 511;
            int r = 2 * bid + half;
            const float4* row4 = (const float4*)&g_scr[r][0];
            float s = 0.f;
            for (int i = lane9; i < V / 4; i += 512) {
                float4 e = __ldcg(&row4[i]);
                s += (e.x + e.y) + (e.z + e.w);
            }
#pragma unroll
            for (int off = 16; off; off >>= 1)
                s += __shfl_down_sync(0xffffffffu, s, off);
            if ((tid & 31) == 0) sred[tid >> 5] = s;
            __syncthreads();
            if ((tid & 511) == 0) {
                float tot = 0.f;
                int w0 = half * 16;
                for (int w = 0; w < 16; w++) tot += sred[w0 + w];
                sInv[half] = 1.f / tot;
                ull key = *(volatile ull*)&g_amax[rp][r];
                __stcg(&g_prev[r], (int)(0xffffffffu - (unsigned)(key & 0xffffffffu)));
            }
            __syncthreads();
            float inv = sInv[half];
            bumpcnt(&c_redq[bid >> 5][0]);   // unblock step t+1 LSTM for this quarter
            float4* orow = (float4*)(out + ((size_t)t * BATCH + r) * V);
            for (int i = lane9; i < V / 4; i += 512) {
                float4 e = __ldcg(&row4[i]);
                float4 o = { e.x * inv, e.y * inv, e.z * inv, e.w * inv };
                __stcs(&orow[i], o);
            }
            if ((tid & 511) == 0) atomicExch(&g_amax[rp][r], 0ull);
        }
        bumpcnt(&c_norm);
    }

    // ---- reset counters for graph replay ----
    __syncthreads();
    if (tid == 0) {
        __threadfence();
        atomicAdd(&c_done, 1);
        if (bid == 0) {
            volatile int* vd = (volatile int*)&c_done;
            while (*vd < NB) __nanosleep(64);
            c_init = 0; c_emb = 0; c_log = 0; c_norm = 0;
            g_mw2key = 0; g_mbkey = 0;
            for (int l = 0; l < NL; l++)
                for (int qq = 0; qq < 4; qq++) c_hq[l][qq][0] = 0;
            for (int qq = 0; qq < 4; qq++) c_redq[qq][0] = 0;
            __threadfence();
            *(volatile int*)&c_done = 0;
        }
    }
}

// ---------------- launch ----------------
extern "C" void kernel_launch(void* const* d_in, const int* in_sizes, int n_in,
                              void* d_out, int out_size) {
    const float* hidden = (const float*)d_in[0];
    const float* cell   = (const float*)d_in[1];
    const float* W_in   = (const float*)d_in[2];
    const float* b_in   = (const float*)d_in[3];
    const float* W_ih   = (const float*)d_in[4];
    const float* W_hh   = (const float*)d_in[5];
    const float* b_ih   = (const float*)d_in[6];
    const float* b_hh   = (const float*)d_in[7];
    const float* W_re   = (const float*)d_in[8];
    const float* b_re   = (const float*)d_in[9];
    const float* W_lo   = (const float*)d_in[10];
    const float* b_lo   = (const float*)d_in[11];
    const int*   eos    = (const int*)d_in[12];
    float* out = (float*)d_out;

    cudaFuncSetAttribute(decoder_kernel, cudaFuncAttributeMaxDynamicSharedMemorySize, SMEM_BYTES);
    decoder_kernel<<<NB, NT, SMEM_BYTES>>>(hidden, cell, W_in, b_in, W_ih, W_hh,
                                           b_ih, b_hh, W_re, b_re, W_lo, b_lo, eos, out);
}